// round 4
// baseline (speedup 1.0000x reference)
#include <cuda_runtime.h>

#define Bn 128
#define Tn 800
#define Hn 256
#define Kw 10
#define An 64

#define NBLK 128
#define NTH  256
#define BH   (Bn * Hn)

// ---------------- persistent device state / scratch ----------------
// Weights stored gate-interleaved: col' = hu*4 + gate  (gate: 0=i,1=f,2=g,3=o)
__device__ float g_W1[324 * 1024];      // rows: [x(3), w(64), h1(256), pad]
__device__ float g_W2[580 * 1024];      // rows: [x, w, h1, h2prev, pad]
__device__ float g_W3[580 * 1024];      // rows: [x, w, h2, h3prev, pad]
__device__ float g_b1[1024], g_b2[1024], g_b3[1024];
__device__ float g_Wh[256 * 121];
__device__ float g_bh[121];

__device__ float g_h1[2][BH];
__device__ float g_h2[2][BH];
__device__ float g_c1[BH], g_c2[BH], g_c3[BH];
__device__ float g_w[2][Bn * An];
__device__ float g_kappa[Bn * Kw];
__device__ float g_zero[BH];
__device__ float g_out[Tn * BH];        // h3 per step [T][B][H]

__device__ unsigned g_bar_cnt = 0;
__device__ volatile unsigned g_bar_gen = 0;

// ---------------- helpers ----------------
__device__ __forceinline__ float sigm(float x) {
    return 1.0f / (1.0f + __expf(-x));
}
__device__ __forceinline__ float tanh_f(float x) {
    float xx = fminf(15.0f, fmaxf(-15.0f, x));
    float t = __expf(-2.0f * xx);
    return (1.0f - t) / (1.0f + t);
}

__device__ __forceinline__ void grid_barrier() {
    __syncthreads();
    if (threadIdx.x == 0) {
        __threadfence();
        unsigned gen = g_bar_gen;
        if (atomicAdd(&g_bar_cnt, 1u) == NBLK - 1u) {
            atomicSub(&g_bar_cnt, (unsigned)NBLK);
            __threadfence();
            g_bar_gen = gen + 1u;
        } else {
            while (g_bar_gen == gen) { __nanosleep(20); }
            __threadfence();
        }
    }
    __syncthreads();
}

// ---------------- shared-memory layout ----------------
struct SmemLay {
    float act[580 * 16];   // transposed activations: [k][16 batches]
    float zs[16 * 64];     // gate pre-activations [16 batches][64 cols]; also attn h1 row
    float aw[30];
    float kap[10];
    float phi[64];
    int   cs[64];
};

// ---------------- LSTM tile: [16 batches x 64 gate-cols], all 128 CTAs ----------------
// cta: btile = cta>>4 (8 tiles of 16 batches), ctile = cta&15 (16 tiles of 64 cols = 16 hu)
template <int KT, int KP>
__device__ void lstm_tile(SmemLay* sm, int cta, const float* __restrict__ x, int t,
                          const float* __restrict__ wv,
                          const float* __restrict__ hA,
                          const float* __restrict__ hB,
                          const float* __restrict__ W,
                          const float* __restrict__ bsum,
                          float* __restrict__ cst,
                          float* __restrict__ hout) {
    const int tid = threadIdx.x;
    const int btile = cta >> 4;
    const int ctile = cta & 15;
    const int b_base = btile * 16;

    // stage activations transposed: act[k][bb]
    for (int idx = tid; idx < KP * 16; idx += NTH) {
        int k = idx >> 4, bb = idx & 15;
        int b = b_base + bb;
        float v = 0.0f;
        if (k < 3)        v = __ldg(&x[(b * Tn + t) * 3 + k]);
        else if (k < 67)  v = __ldcv(&wv[b * 64 + (k - 3)]);
        else if (k < 323) v = __ldcv(&hA[(b << 8) + (k - 67)]);
        else if (k < KT)  v = __ldcv(&hB[(b << 8) + (k - 323)]);
        sm->act[idx] = v;
    }
    __syncthreads();

    // GEMM: thread = 1 gate-col x 4 batches. Warp lanes = 32 consecutive cols -> 1 line/LDG.
    const int cg = tid & 63;
    const int bg = tid >> 6;           // 0..3
    const int colp = ctile * 64 + cg;
    const float* Wc = W + colp;
    const float* ap = sm->act + bg * 4;

    float a0 = 0.f, a1 = 0.f, a2 = 0.f, a3 = 0.f;
#pragma unroll 8
    for (int k = 0; k < KP; k++) {
        float wq = __ldg(&Wc[k << 10]);
        float4 av = *reinterpret_cast<const float4*>(ap + (k << 4));
        a0 = fmaf(wq, av.x, a0);
        a1 = fmaf(wq, av.y, a1);
        a2 = fmaf(wq, av.z, a2);
        a3 = fmaf(wq, av.w, a3);
    }
    float bias = __ldg(&bsum[colp]);
    sm->zs[(bg * 4 + 0) * 64 + cg] = a0 + bias;
    sm->zs[(bg * 4 + 1) * 64 + cg] = a1 + bias;
    sm->zs[(bg * 4 + 2) * 64 + cg] = a2 + bias;
    sm->zs[(bg * 4 + 3) * 64 + cg] = a3 + bias;
    __syncthreads();

    // cell update: 256 (b,hu) pairs, 1 per thread
    {
        int b_loc = tid >> 4, hu_loc = tid & 15;
        int hu = ctile * 16 + hu_loc;
        int b = b_base + b_loc;
        float zi = sm->zs[b_loc * 64 + hu_loc * 4 + 0];
        float zf = sm->zs[b_loc * 64 + hu_loc * 4 + 1];
        float zg = sm->zs[b_loc * 64 + hu_loc * 4 + 2];
        float zo = sm->zs[b_loc * 64 + hu_loc * 4 + 3];
        int ix = (b << 8) + hu;
        float cp = cst[ix];
        float ig = sigm(zi), fg = sigm(zf), og = sigm(zo);
        float gg = tanh_f(zg);
        float cn = fmaf(fg, cp, ig * gg);
        cst[ix] = cn;
        hout[ix] = og * tanh_f(cn);
    }
    __syncthreads();
}

// ---------------- attention: 1 batch per CTA ----------------
__device__ void attn_tile(SmemLay* sm, int b, const float* __restrict__ h1,
                          float* __restrict__ wout,
                          const int* __restrict__ cidx,
                          const float* __restrict__ Ww,
                          const float* __restrict__ bw) {
    const int tt = threadIdx.x;
    // stage h1 row in zs[0..255]
    sm->zs[tt] = __ldcv(&h1[(b << 8) + tt]);
    if (tt < 64) sm->cs[tt] = __ldg(&cidx[b * 64 + tt]);
    __syncthreads();

    if (tt < 30) {
        float z = __ldg(&bw[tt]);
#pragma unroll 8
        for (int i = 0; i < 256; i++)
            z = fmaf(sm->zs[i], __ldg(&Ww[i * 30 + tt]), z);
        sm->aw[tt] = __expf(z);
    }
    __syncthreads();

    if (tt < 10) {
        float kn = fmaf(0.1f, sm->aw[20 + tt], g_kappa[b * 10 + tt]);
        g_kappa[b * 10 + tt] = kn;
        sm->kap[tt] = kn;
    }
    __syncthreads();

    if (tt < 64) {
        float uu = (float)tt, phi = 0.0f;
#pragma unroll
        for (int k = 0; k < 10; k++) {
            float d = sm->kap[k] - uu;
            phi = fmaf(sm->aw[k], __expf(-sm->aw[10 + k] * d * d), phi);
        }
        sm->phi[tt] = phi;
    }
    __syncthreads();

    if (tt < 64) {
        float s = 0.0f;
        for (int u = 0; u < 64; u++)
            if (sm->cs[u] == tt) s += sm->phi[u];
        wout[b * 64 + tt] = s;
    }
    __syncthreads();
}

// ---------------- persistent RNN kernel ----------------
__global__ void __launch_bounds__(NTH)
rnn_kernel(const float* __restrict__ x, const int* __restrict__ cidx,
           const float* __restrict__ Ww, const float* __restrict__ bw) {
    __shared__ SmemLay sm;
    const int cta = blockIdx.x;
    const int tid = threadIdx.x;

    // re-init recurrent state every launch (graph replays!)
    {
        int g0 = cta * NTH + tid;
        int gsz = NBLK * NTH;
        for (int p = g0; p < BH; p += gsz) {
            g_h1[0][p] = 0.f; g_h1[1][p] = 0.f;
            g_h2[0][p] = 0.f; g_h2[1][p] = 0.f;
            g_c1[p] = 0.f; g_c2[p] = 0.f; g_c3[p] = 0.f;
            g_zero[p] = 0.f;
        }
        for (int p = g0; p < Bn * An; p += gsz) { g_w[0][p] = 0.f; g_w[1][p] = 1.0f; }
        for (int p = g0; p < Bn * Kw; p += gsz) g_kappa[p] = 0.f;
    }
    grid_barrier();

    // prologue: LSTM1(0): w(-1)=ones (g_w[1]), h1(-1)=0 -> h1(0)=g_h1[0]
    lstm_tile<323, 324>(&sm, cta, x, 0, g_w[1], g_h1[1], g_zero,
                        g_W1, g_b1, g_c1, g_h1[0]);
    grid_barrier();
    attn_tile(&sm, cta, g_h1[0], g_w[0], cidx, Ww, bw);
    grid_barrier();

    for (int t = 0; t < Tn; t++) {
        const int p = t & 1, pn = (t + 1) & 1;

        // slot A: LSTM2(t) then LSTM1(t+1)
        lstm_tile<579, 580>(&sm, cta, x, t, g_w[p], g_h1[p], g_h2[pn],
                            g_W2, g_b2, g_c2, g_h2[p]);
        if (t + 1 < Tn)
            lstm_tile<323, 324>(&sm, cta, x, t + 1, g_w[p], g_h1[p], g_zero,
                                g_W1, g_b1, g_c1, g_h1[pn]);
        grid_barrier();

        // slot B: LSTM3(t) then Attn(t+1)
        {
            const float* h3prev = (t > 0) ? (g_out + (t - 1) * BH) : g_zero;
            lstm_tile<579, 580>(&sm, cta, x, t, g_w[p], g_h2[p], h3prev,
                                g_W3, g_b3, g_c3, g_out + t * BH);
        }
        if (t + 1 < Tn)
            attn_tile(&sm, cta, g_h1[pn], g_w[pn], cidx, Ww, bw);
        grid_barrier();
    }
}

// ---------------- weight pre-pack kernel (gate-interleaved cols) ----------------
__global__ void prep_kernel(
    const float* Wih1, const float* Whh1, const float* bih1, const float* bhh1,
    const float* Wih2, const float* Whh2, const float* bih2, const float* bhh2,
    const float* Wih3, const float* Whh3, const float* bih3, const float* bhh3,
    const float* We, const float* be, const float* Wpi, const float* bpi,
    const float* Wmu1, const float* bmu1, const float* Wmu2, const float* bmu2,
    const float* Ws1, const float* bs1, const float* Ws2, const float* bs2,
    const float* Wrho, const float* brho) {
    int g0 = blockIdx.x * blockDim.x + threadIdx.x;
    int gsz = gridDim.x * blockDim.x;

    for (int pidx = g0; pidx < 324 * 1024; pidx += gsz) {
        int i = pidx >> 10, colp = pidx & 1023;
        int hu = colp >> 2, g = colp & 3;
        int j = g * 256 + hu;
        float v = 0.f;
        if (i < 67) v = Wih1[i * 1024 + j];
        else if (i < 323) v = Whh1[(i - 67) * 1024 + j];
        g_W1[pidx] = v;
    }
    for (int pidx = g0; pidx < 580 * 1024; pidx += gsz) {
        int i = pidx >> 10, colp = pidx & 1023;
        int hu = colp >> 2, g = colp & 3;
        int j = g * 256 + hu;
        float v2 = 0.f, v3 = 0.f;
        if (i < 323) { v2 = Wih2[i * 1024 + j]; v3 = Wih3[i * 1024 + j]; }
        else if (i < 579) {
            v2 = Whh2[(i - 323) * 1024 + j];
            v3 = Whh3[(i - 323) * 1024 + j];
        }
        g_W2[pidx] = v2;
        g_W3[pidx] = v3;
    }
    for (int colp = g0; colp < 1024; colp += gsz) {
        int hu = colp >> 2, g = colp & 3;
        int j = g * 256 + hu;
        g_b1[colp] = bih1[j] + bhh1[j];
        g_b2[colp] = bih2[j] + bhh2[j];
        g_b3[colp] = bih3[j] + bhh3[j];
    }
    for (int pidx = g0; pidx < 256 * 121; pidx += gsz) {
        int i = pidx / 121, col = pidx - i * 121;
        float v;
        if (col == 0)       v = We[i];
        else if (col < 21)  v = Wpi[i * 20 + (col - 1)];
        else if (col < 41)  v = Wmu1[i * 20 + (col - 21)];
        else if (col < 61)  v = Wmu2[i * 20 + (col - 41)];
        else if (col < 81)  v = Ws1[i * 20 + (col - 61)];
        else if (col < 101) v = Ws2[i * 20 + (col - 81)];
        else                v = Wrho[i * 20 + (col - 101)];
        g_Wh[pidx] = v;
    }
    for (int col = g0; col < 121; col += gsz) {
        float v;
        if (col == 0)       v = be[0];
        else if (col < 21)  v = bpi[col - 1];
        else if (col < 41)  v = bmu1[col - 21];
        else if (col < 61)  v = bmu2[col - 41];
        else if (col < 81)  v = bs1[col - 61];
        else if (col < 101) v = bs2[col - 81];
        else                v = brho[col - 101];
        g_bh[col] = v;
    }
}

// ---------------- MDN heads kernel ----------------
__global__ void __launch_bounds__(128)
heads_kernel(float* __restrict__ out) {
    __shared__ __align__(16) float hs[32 * 256];
    __shared__ float pz[32][20];
    const int r0 = blockIdx.x * 32;
    const int tid = threadIdx.x;

    {
        const float4* src = reinterpret_cast<const float4*>(g_out + r0 * 256);
        float4* dst = reinterpret_cast<float4*>(hs);
        for (int pidx = tid; pidx < 32 * 64; pidx += 128) dst[pidx] = src[pidx];
    }
    __syncthreads();

    const int j = tid;
    float acc[32];
    if (j < 121) {
#pragma unroll
        for (int r = 0; r < 32; r++) acc[r] = 0.0f;
#pragma unroll 2
        for (int i4 = 0; i4 < 64; i4++) {
            float w0 = g_Wh[(i4 * 4 + 0) * 121 + j];
            float w1 = g_Wh[(i4 * 4 + 1) * 121 + j];
            float w2 = g_Wh[(i4 * 4 + 2) * 121 + j];
            float w3 = g_Wh[(i4 * 4 + 3) * 121 + j];
#pragma unroll
            for (int r = 0; r < 32; r++) {
                float4 hv = reinterpret_cast<const float4*>(hs + r * 256)[i4];
                acc[r] = fmaf(hv.x, w0, fmaf(hv.y, w1, fmaf(hv.z, w2, fmaf(hv.w, w3, acc[r]))));
            }
        }
        float bias = g_bh[j];
#pragma unroll
        for (int r = 0; r < 32; r++) acc[r] += bias;
        if (j >= 1 && j < 21)
            for (int r = 0; r < 32; r++) pz[r][j - 1] = acc[r];
    }
    __syncthreads();

    if (j < 121) {
        const int TB = Tn * Bn;
        float* es  = out;
        float* pi  = out + TB;
        float* mu1 = out + TB + TB * 20;
        float* mu2 = mu1 + TB * 20;
        float* s1  = mu2 + TB * 20;
        float* s2  = s1 + TB * 20;
        float* rh  = s2 + TB * 20;
        for (int r = 0; r < 32; r++) {
            int gr = r0 + r;
            float z = acc[r];
            if (j == 0) {
                es[gr] = 1.0f / (1.0f + __expf(z));
            } else if (j < 21) {
                float m = -1e30f;
                for (int k = 0; k < 20; k++) m = fmaxf(m, pz[r][k]);
                float s = 0.f;
                for (int k = 0; k < 20; k++) s += __expf(pz[r][k] - m);
                pi[gr * 20 + (j - 1)] = __expf(z - m) / s;
            } else if (j < 41) {
                mu1[gr * 20 + (j - 21)] = z;
            } else if (j < 61) {
                mu2[gr * 20 + (j - 41)] = z;
            } else if (j < 81) {
                s1[gr * 20 + (j - 61)] = __expf(z);
            } else if (j < 101) {
                s2[gr * 20 + (j - 81)] = __expf(z);
            } else {
                rh[gr * 20 + (j - 101)] = tanh_f(z);
            }
        }
    }
}

// ---------------- launch ----------------
extern "C" void kernel_launch(void* const* d_in, const int* in_sizes, int n_in,
                              void* d_out, int out_size) {
    const float* x    = (const float*)d_in[0];
    const int*   c    = (const int*)d_in[1];
    const float* Wih1 = (const float*)d_in[2];
    const float* Whh1 = (const float*)d_in[3];
    const float* bih1 = (const float*)d_in[4];
    const float* bhh1 = (const float*)d_in[5];
    const float* Wih2 = (const float*)d_in[6];
    const float* Whh2 = (const float*)d_in[7];
    const float* bih2 = (const float*)d_in[8];
    const float* bhh2 = (const float*)d_in[9];
    const float* Wih3 = (const float*)d_in[10];
    const float* Whh3 = (const float*)d_in[11];
    const float* bih3 = (const float*)d_in[12];
    const float* bhh3 = (const float*)d_in[13];
    const float* Ww   = (const float*)d_in[14];
    const float* bw   = (const float*)d_in[15];
    const float* We   = (const float*)d_in[16];
    const float* be   = (const float*)d_in[17];
    const float* Wpi  = (const float*)d_in[18];
    const float* bpi  = (const float*)d_in[19];
    const float* Wmu1 = (const float*)d_in[20];
    const float* bmu1 = (const float*)d_in[21];
    const float* Wmu2 = (const float*)d_in[22];
    const float* bmu2 = (const float*)d_in[23];
    const float* Ws1  = (const float*)d_in[24];
    const float* bs1  = (const float*)d_in[25];
    const float* Ws2  = (const float*)d_in[26];
    const float* bs2  = (const float*)d_in[27];
    const float* Wrho = (const float*)d_in[28];
    const float* brho = (const float*)d_in[29];

    prep_kernel<<<512, 256>>>(Wih1, Whh1, bih1, bhh1,
                              Wih2, Whh2, bih2, bhh2,
                              Wih3, Whh3, bih3, bhh3,
                              We, be, Wpi, bpi, Wmu1, bmu1, Wmu2, bmu2,
                              Ws1, bs1, Ws2, bs2, Wrho, brho);
    rnn_kernel<<<NBLK, NTH>>>(x, c, Ww, bw);
    heads_kernel<<<(Tn * Bn) / 32, 128>>>((float*)d_out);
}

// round 5
// speedup vs baseline: 1.2952x; 1.2952x over previous
#include <cuda_runtime.h>

#define Bn 128
#define Tn 800
#define Hn 256
#define Kw 10
#define An 64

#define NBLK 128
#define NTH  256
#define BH   (Bn * Hn)

// dynamic smem layout (bytes)
#define W_OFF   0            // 3 chunks x 64x64 floats = 49152
#define ACT_OFF 49152        // 640*16 floats = 40960
#define ZS_OFF  90112        // 16*64 floats = 4096
#define AW_OFF  94208        // attn scratch
#define SMEM_BYTES 98304

// ---------------- persistent device state / scratch ----------------
// Weights gate-interleaved: col' = hu*4 + gate. Rows zero-padded to 384/640.
__device__ float g_W1[384 * 1024];      // rows: [x(3), w(64), h1(256), pad->384]
__device__ float g_W2[640 * 1024];      // rows: [x, w, h1, h2prev, pad->640]
__device__ float g_W3[640 * 1024];      // rows: [x, w, h2, h3prev, pad->640]
__device__ float g_b1[1024], g_b2[1024], g_b3[1024];
__device__ float g_Wh[256 * 121];
__device__ float g_bh[121];

__device__ float g_h1[2][BH];
__device__ float g_h2[2][BH];
__device__ float g_c1[BH], g_c2[BH], g_c3[BH];
__device__ float g_w[2][Bn * An];
__device__ float g_kappa[Bn * Kw];
__device__ float g_zero[BH];
__device__ float g_out[Tn * BH];        // h3 per step [T][B][H]

__device__ unsigned g_bar_cnt = 0;
__device__ volatile unsigned g_bar_gen = 0;

// ---------------- helpers ----------------
__device__ __forceinline__ float sigm(float x) {
    return 1.0f / (1.0f + __expf(-x));
}
__device__ __forceinline__ float tanh_f(float x) {
    float xx = fminf(15.0f, fmaxf(-15.0f, x));
    float t = __expf(-2.0f * xx);
    return (1.0f - t) / (1.0f + t);
}

__device__ __forceinline__ void grid_barrier() {
    __syncthreads();
    if (threadIdx.x == 0) {
        __threadfence();
        unsigned gen = g_bar_gen;
        if (atomicAdd(&g_bar_cnt, 1u) == NBLK - 1u) {
            atomicSub(&g_bar_cnt, (unsigned)NBLK);
            __threadfence();
            g_bar_gen = gen + 1u;
        } else {
            while (g_bar_gen == gen) { __nanosleep(20); }
            __threadfence();
        }
    }
    __syncthreads();
}

// copy one 64-row x 64-col weight chunk (16KB) global->smem via cp.async
__device__ __forceinline__ void cp_chunk(unsigned dst_u32, const float* __restrict__ Wg,
                                         int colp0, int k0) {
    const int tid = threadIdx.x;
#pragma unroll
    for (int i = 0; i < 4; i++) {
        int idx = tid + i * NTH;             // 0..1023
        int row = idx >> 4;
        int c4 = (idx & 15) << 2;
        const float* src = Wg + (k0 + row) * 1024 + colp0 + c4;
        unsigned d = dst_u32 + (unsigned)((row * 64 + c4) * 4);
        asm volatile("cp.async.cg.shared.global [%0], [%1], 16;" :: "r"(d), "l"(src));
    }
    asm volatile("cp.async.commit_group;" ::: "memory");
}

// ---------------- LSTM tile: [16 batches x 64 gate-cols], all 128 CTAs ----------------
// cta: btile = cta>>4, ctile = cta&15. Weight tile streamed via 3-deep cp.async pipe.
template <int KT, int KP, int NCH>
__device__ void lstm_tile(float* sm, unsigned sm_u32, int cta,
                          const float* __restrict__ x, int t,
                          const float* __restrict__ wv,
                          const float* __restrict__ hA,
                          const float* __restrict__ hB,
                          const float* __restrict__ Wg,
                          const float* __restrict__ bsum,
                          float* __restrict__ cst,
                          float* __restrict__ hout) {
    const int tid = threadIdx.x;
    const int btile = cta >> 4;
    const int ctile = cta & 15;
    const int b_base = btile * 16;
    const int colp0 = ctile * 64;

    float* sact = sm + ACT_OFF / 4;
    float* szs  = sm + ZS_OFF / 4;

    // kick off the first 3 weight chunks
    cp_chunk(sm_u32 + W_OFF + 0 * 16384, Wg, colp0, 0);
    cp_chunk(sm_u32 + W_OFF + 1 * 16384, Wg, colp0, 64);
    cp_chunk(sm_u32 + W_OFF + 2 * 16384, Wg, colp0, 128);

    // stage activations transposed: act[k][bb], zero-padded to KP rows
    for (int idx = tid; idx < KP * 16; idx += NTH) {
        int k = idx >> 4, bb = idx & 15;
        int b = b_base + bb;
        float v = 0.0f;
        if (k < 3)        v = __ldg(&x[(b * Tn + t) * 3 + k]);
        else if (k < 67)  v = __ldcv(&wv[b * 64 + (k - 3)]);
        else if (k < 323) v = __ldcv(&hA[(b << 8) + (k - 67)]);
        else if (k < KT)  v = __ldcv(&hB[(b << 8) + (k - 323)]);
        sact[idx] = v;
    }

    const int cg = tid & 63;            // gate-col within tile
    const int bg = tid >> 6;            // batch group (4 batches)
    unsigned long long acc01 = 0ull, acc23 = 0ull;   // packed f32x2 accumulators

    for (int c = 0; c < NCH; c++) {
        asm volatile("cp.async.wait_group 2;" ::: "memory");
        __syncthreads();                 // chunk c visible; act staged (c==0)
        const float* wb = sm + (W_OFF / 4) + (c % 3) * 4096;
        const char* apb = (const char*)(sact + c * 64 * 16 + bg * 4);
#pragma unroll 16
        for (int k2 = 0; k2 < 64; k2++) {
            float w = wb[k2 * 64 + cg];
            ulonglong2 av = *reinterpret_cast<const ulonglong2*>(apb + k2 * 64);
            unsigned long long wp;
            asm("mov.b64 %0, {%1, %1};" : "=l"(wp) : "f"(w));
            asm("fma.rn.f32x2 %0, %1, %2, %0;" : "+l"(acc01) : "l"(av.x), "l"(wp));
            asm("fma.rn.f32x2 %0, %1, %2, %0;" : "+l"(acc23) : "l"(av.y), "l"(wp));
        }
        __syncthreads();                 // all warps done with buf (c%3)
        if (c + 3 < NCH)
            cp_chunk(sm_u32 + W_OFF + ((c + 3) % 3) * 16384, Wg, colp0, (c + 3) * 64);
        else
            asm volatile("cp.async.commit_group;" ::: "memory");  // empty group keeps count
    }

    float a0, a1, a2, a3;
    asm("mov.b64 {%0, %1}, %2;" : "=f"(a0), "=f"(a1) : "l"(acc01));
    asm("mov.b64 {%0, %1}, %2;" : "=f"(a2), "=f"(a3) : "l"(acc23));
    float bias = __ldg(&bsum[colp0 + cg]);
    szs[(bg * 4 + 0) * 64 + cg] = a0 + bias;
    szs[(bg * 4 + 1) * 64 + cg] = a1 + bias;
    szs[(bg * 4 + 2) * 64 + cg] = a2 + bias;
    szs[(bg * 4 + 3) * 64 + cg] = a3 + bias;
    __syncthreads();

    // cell update: 256 (b,hu) pairs, 1 per thread
    {
        int b_loc = tid >> 4, hu_loc = tid & 15;
        int hu = ctile * 16 + hu_loc;
        int b = b_base + b_loc;
        float zi = szs[b_loc * 64 + hu_loc * 4 + 0];
        float zf = szs[b_loc * 64 + hu_loc * 4 + 1];
        float zg = szs[b_loc * 64 + hu_loc * 4 + 2];
        float zo = szs[b_loc * 64 + hu_loc * 4 + 3];
        int ix = (b << 8) + hu;
        float cp = cst[ix];
        float ig = sigm(zi), fg = sigm(zf), og = sigm(zo);
        float gg = tanh_f(zg);
        float cn = fmaf(fg, cp, ig * gg);
        cst[ix] = cn;
        hout[ix] = og * tanh_f(cn);
    }
    __syncthreads();
}

// ---------------- attention: 1 batch per CTA ----------------
__device__ void attn_tile(float* sm, int b, const float* __restrict__ h1,
                          float* __restrict__ wout,
                          const int* __restrict__ cidx,
                          const float* __restrict__ Ww,
                          const float* __restrict__ bw) {
    float* hrow = sm + ZS_OFF / 4;      // 256 floats
    float* aw   = sm + AW_OFF / 4;      // 30
    float* kap  = aw + 32;              // 10
    float* phi  = kap + 16;             // 64
    int*   cs   = (int*)(phi + 64);     // 64
    const int tt = threadIdx.x;

    hrow[tt] = __ldcv(&h1[(b << 8) + tt]);
    if (tt < 64) cs[tt] = __ldg(&cidx[b * 64 + tt]);
    __syncthreads();

    if (tt < 30) {
        float z = __ldg(&bw[tt]);
#pragma unroll 8
        for (int i = 0; i < 256; i++)
            z = fmaf(hrow[i], __ldg(&Ww[i * 30 + tt]), z);
        aw[tt] = __expf(z);
    }
    __syncthreads();

    if (tt < 10) {
        float kn = fmaf(0.1f, aw[20 + tt], g_kappa[b * 10 + tt]);
        g_kappa[b * 10 + tt] = kn;
        kap[tt] = kn;
    }
    __syncthreads();

    if (tt < 64) {
        float uu = (float)tt, ph = 0.0f;
#pragma unroll
        for (int k = 0; k < 10; k++) {
            float d = kap[k] - uu;
            ph = fmaf(aw[k], __expf(-aw[10 + k] * d * d), ph);
        }
        phi[tt] = ph;
    }
    __syncthreads();

    if (tt < 64) {
        float s = 0.0f;
        for (int u = 0; u < 64; u++)
            if (cs[u] == tt) s += phi[u];
        wout[b * 64 + tt] = s;
    }
    __syncthreads();
}

// ---------------- persistent RNN kernel ----------------
__global__ void __launch_bounds__(NTH)
rnn_kernel(const float* __restrict__ x, const int* __restrict__ cidx,
           const float* __restrict__ Ww, const float* __restrict__ bw) {
    extern __shared__ float sm[];
    unsigned sm_u32 = (unsigned)__cvta_generic_to_shared(sm);
    const int cta = blockIdx.x;
    const int tid = threadIdx.x;

    // re-init recurrent state every launch (graph replays!)
    {
        int g0 = cta * NTH + tid;
        int gsz = NBLK * NTH;
        for (int p = g0; p < BH; p += gsz) {
            g_h1[0][p] = 0.f; g_h1[1][p] = 0.f;
            g_h2[0][p] = 0.f; g_h2[1][p] = 0.f;
            g_c1[p] = 0.f; g_c2[p] = 0.f; g_c3[p] = 0.f;
            g_zero[p] = 0.f;
        }
        for (int p = g0; p < Bn * An; p += gsz) { g_w[0][p] = 0.f; g_w[1][p] = 1.0f; }
        for (int p = g0; p < Bn * Kw; p += gsz) g_kappa[p] = 0.f;
    }
    grid_barrier();

    // prologue: LSTM1(0): w(-1)=ones (g_w[1]), h1(-1)=0 -> h1(0)=g_h1[0]
    lstm_tile<323, 384, 6>(sm, sm_u32, cta, x, 0, g_w[1], g_h1[1], g_zero,
                           g_W1, g_b1, g_c1, g_h1[0]);
    grid_barrier();
    attn_tile(sm, cta, g_h1[0], g_w[0], cidx, Ww, bw);
    grid_barrier();

    for (int t = 0; t < Tn; t++) {
        const int p = t & 1, pn = (t + 1) & 1;

        // slot A: LSTM2(t) then LSTM1(t+1)
        lstm_tile<579, 640, 10>(sm, sm_u32, cta, x, t, g_w[p], g_h1[p], g_h2[pn],
                                g_W2, g_b2, g_c2, g_h2[p]);
        if (t + 1 < Tn)
            lstm_tile<323, 384, 6>(sm, sm_u32, cta, x, t + 1, g_w[p], g_h1[p], g_zero,
                                   g_W1, g_b1, g_c1, g_h1[pn]);
        grid_barrier();

        // slot B: LSTM3(t) then Attn(t+1)
        {
            const float* h3prev = (t > 0) ? (g_out + (t - 1) * BH) : g_zero;
            lstm_tile<579, 640, 10>(sm, sm_u32, cta, x, t, g_w[p], g_h2[p], h3prev,
                                    g_W3, g_b3, g_c3, g_out + t * BH);
        }
        if (t + 1 < Tn)
            attn_tile(sm, cta, g_h1[pn], g_w[pn], cidx, Ww, bw);
        grid_barrier();
    }
}

// ---------------- weight pre-pack kernel (gate-interleaved cols, row-padded) ----------------
__global__ void prep_kernel(
    const float* Wih1, const float* Whh1, const float* bih1, const float* bhh1,
    const float* Wih2, const float* Whh2, const float* bih2, const float* bhh2,
    const float* Wih3, const float* Whh3, const float* bih3, const float* bhh3,
    const float* We, const float* be, const float* Wpi, const float* bpi,
    const float* Wmu1, const float* bmu1, const float* Wmu2, const float* bmu2,
    const float* Ws1, const float* bs1, const float* Ws2, const float* bs2,
    const float* Wrho, const float* brho) {
    int g0 = blockIdx.x * blockDim.x + threadIdx.x;
    int gsz = gridDim.x * blockDim.x;

    for (int pidx = g0; pidx < 384 * 1024; pidx += gsz) {
        int i = pidx >> 10, colp = pidx & 1023;
        int hu = colp >> 2, g = colp & 3;
        int j = g * 256 + hu;
        float v = 0.f;
        if (i < 67) v = Wih1[i * 1024 + j];
        else if (i < 323) v = Whh1[(i - 67) * 1024 + j];
        g_W1[pidx] = v;
    }
    for (int pidx = g0; pidx < 640 * 1024; pidx += gsz) {
        int i = pidx >> 10, colp = pidx & 1023;
        int hu = colp >> 2, g = colp & 3;
        int j = g * 256 + hu;
        float v2 = 0.f, v3 = 0.f;
        if (i < 323) { v2 = Wih2[i * 1024 + j]; v3 = Wih3[i * 1024 + j]; }
        else if (i < 579) {
            v2 = Whh2[(i - 323) * 1024 + j];
            v3 = Whh3[(i - 323) * 1024 + j];
        }
        g_W2[pidx] = v2;
        g_W3[pidx] = v3;
    }
    for (int colp = g0; colp < 1024; colp += gsz) {
        int hu = colp >> 2, g = colp & 3;
        int j = g * 256 + hu;
        g_b1[colp] = bih1[j] + bhh1[j];
        g_b2[colp] = bih2[j] + bhh2[j];
        g_b3[colp] = bih3[j] + bhh3[j];
    }
    for (int pidx = g0; pidx < 256 * 121; pidx += gsz) {
        int i = pidx / 121, col = pidx - i * 121;
        float v;
        if (col == 0)       v = We[i];
        else if (col < 21)  v = Wpi[i * 20 + (col - 1)];
        else if (col < 41)  v = Wmu1[i * 20 + (col - 21)];
        else if (col < 61)  v = Wmu2[i * 20 + (col - 41)];
        else if (col < 81)  v = Ws1[i * 20 + (col - 61)];
        else if (col < 101) v = Ws2[i * 20 + (col - 81)];
        else                v = Wrho[i * 20 + (col - 101)];
        g_Wh[pidx] = v;
    }
    for (int col = g0; col < 121; col += gsz) {
        float v;
        if (col == 0)       v = be[0];
        else if (col < 21)  v = bpi[col - 1];
        else if (col < 41)  v = bmu1[col - 21];
        else if (col < 61)  v = bmu2[col - 41];
        else if (col < 81)  v = bs1[col - 61];
        else if (col < 101) v = bs2[col - 81];
        else                v = brho[col - 101];
        g_bh[col] = v;
    }
}

// ---------------- MDN heads kernel ----------------
__global__ void __launch_bounds__(128)
heads_kernel(float* __restrict__ out) {
    __shared__ __align__(16) float hs[32 * 256];
    __shared__ float pz[32][20];
    const int r0 = blockIdx.x * 32;
    const int tid = threadIdx.x;

    {
        const float4* src = reinterpret_cast<const float4*>(g_out + r0 * 256);
        float4* dst = reinterpret_cast<float4*>(hs);
        for (int pidx = tid; pidx < 32 * 64; pidx += 128) dst[pidx] = src[pidx];
    }
    __syncthreads();

    const int j = tid;
    float acc[32];
    if (j < 121) {
#pragma unroll
        for (int r = 0; r < 32; r++) acc[r] = 0.0f;
#pragma unroll 2
        for (int i4 = 0; i4 < 64; i4++) {
            float w0 = g_Wh[(i4 * 4 + 0) * 121 + j];
            float w1 = g_Wh[(i4 * 4 + 1) * 121 + j];
            float w2 = g_Wh[(i4 * 4 + 2) * 121 + j];
            float w3 = g_Wh[(i4 * 4 + 3) * 121 + j];
#pragma unroll
            for (int r = 0; r < 32; r++) {
                float4 hv = reinterpret_cast<const float4*>(hs + r * 256)[i4];
                acc[r] = fmaf(hv.x, w0, fmaf(hv.y, w1, fmaf(hv.z, w2, fmaf(hv.w, w3, acc[r]))));
            }
        }
        float bias = g_bh[j];
#pragma unroll
        for (int r = 0; r < 32; r++) acc[r] += bias;
        if (j >= 1 && j < 21)
            for (int r = 0; r < 32; r++) pz[r][j - 1] = acc[r];
    }
    __syncthreads();

    if (j < 121) {
        const int TB = Tn * Bn;
        float* es  = out;
        float* pi  = out + TB;
        float* mu1 = out + TB + TB * 20;
        float* mu2 = mu1 + TB * 20;
        float* s1  = mu2 + TB * 20;
        float* s2  = s1 + TB * 20;
        float* rh  = s2 + TB * 20;
        for (int r = 0; r < 32; r++) {
            int gr = r0 + r;
            float z = acc[r];
            if (j == 0) {
                es[gr] = 1.0f / (1.0f + __expf(z));
            } else if (j < 21) {
                float m = -1e30f;
                for (int k = 0; k < 20; k++) m = fmaxf(m, pz[r][k]);
                float s = 0.f;
                for (int k = 0; k < 20; k++) s += __expf(pz[r][k] - m);
                pi[gr * 20 + (j - 1)] = __expf(z - m) / s;
            } else if (j < 41) {
                mu1[gr * 20 + (j - 21)] = z;
            } else if (j < 61) {
                mu2[gr * 20 + (j - 41)] = z;
            } else if (j < 81) {
                s1[gr * 20 + (j - 61)] = __expf(z);
            } else if (j < 101) {
                s2[gr * 20 + (j - 81)] = __expf(z);
            } else {
                rh[gr * 20 + (j - 101)] = tanh_f(z);
            }
        }
    }
}

// ---------------- launch ----------------
extern "C" void kernel_launch(void* const* d_in, const int* in_sizes, int n_in,
                              void* d_out, int out_size) {
    const float* x    = (const float*)d_in[0];
    const int*   c    = (const int*)d_in[1];
    const float* Wih1 = (const float*)d_in[2];
    const float* Whh1 = (const float*)d_in[3];
    const float* bih1 = (const float*)d_in[4];
    const float* bhh1 = (const float*)d_in[5];
    const float* Wih2 = (const float*)d_in[6];
    const float* Whh2 = (const float*)d_in[7];
    const float* bih2 = (const float*)d_in[8];
    const float* bhh2 = (const float*)d_in[9];
    const float* Wih3 = (const float*)d_in[10];
    const float* Whh3 = (const float*)d_in[11];
    const float* bih3 = (const float*)d_in[12];
    const float* bhh3 = (const float*)d_in[13];
    const float* Ww   = (const float*)d_in[14];
    const float* bw   = (const float*)d_in[15];
    const float* We   = (const float*)d_in[16];
    const float* be   = (const float*)d_in[17];
    const float* Wpi  = (const float*)d_in[18];
    const float* bpi  = (const float*)d_in[19];
    const float* Wmu1 = (const float*)d_in[20];
    const float* bmu1 = (const float*)d_in[21];
    const float* Wmu2 = (const float*)d_in[22];
    const float* bmu2 = (const float*)d_in[23];
    const float* Ws1  = (const float*)d_in[24];
    const float* bs1  = (const float*)d_in[25];
    const float* Ws2  = (const float*)d_in[26];
    const float* bs2  = (const float*)d_in[27];
    const float* Wrho = (const float*)d_in[28];
    const float* brho = (const float*)d_in[29];

    cudaFuncSetAttribute(rnn_kernel, cudaFuncAttributeMaxDynamicSharedMemorySize,
                         SMEM_BYTES);

    prep_kernel<<<512, 256>>>(Wih1, Whh1, bih1, bhh1,
                              Wih2, Whh2, bih2, bhh2,
                              Wih3, Whh3, bih3, bhh3,
                              We, be, Wpi, bpi, Wmu1, bmu1, Wmu2, bmu2,
                              Ws1, bs1, Ws2, bs2, Wrho, brho);
    rnn_kernel<<<NBLK, NTH, SMEM_BYTES>>>(x, c, Ww, bw);
    heads_kernel<<<(Tn * Bn) / 32, 128>>>((float*)d_out);
}

// round 6
// speedup vs baseline: 2.2078x; 1.7046x over previous
#include <cuda_runtime.h>

#define Bn 128
#define Tn 800
#define Hn 256
#define Kw 10
#define An 64

#define NBLK 128
#define NTH  256
#define BH   (Bn * Hn)

// smem layout in floats
#define WT_OFF   0               // 3 bufs x (64 cols x 68 words) = 13056
#define ACT_OFF  13056           // 16 rows x 644 = 10304
#define ZS_OFF   23360           // 1024
#define ATTN_OFF 24384           // 672
#define SMEM_FLOATS 25056
#define SMEM_BYTES  (SMEM_FLOATS * 4)

#define ACT_STRIDE 644
#define WBUF_FLOATS 4352         // 64*68

// ---------------- persistent device state / scratch ----------------
// Weights transposed col-major: g_Wt[colp][feat], colp = hu*4+gate.
// feature order: [x0..x2, pad, w(64), hA(256), hB(256), pad...]
__device__ float g_W1t[1024 * 384];
__device__ float g_W2t[1024 * 640];
__device__ float g_W3t[1024 * 640];
__device__ float g_b1[1024], g_b2[1024], g_b3[1024];
__device__ float g_Wh[256 * 121];
__device__ float g_bh[121];

__device__ float g_h1[2][BH];
__device__ float g_h2[2][BH];
__device__ float g_c1[BH], g_c2[BH], g_c3[BH];
__device__ float g_w[2][Bn * An];
__device__ float g_kappa[Bn * Kw];
__device__ float g_zero[BH];
__device__ float g_out[Tn * BH];        // h3 per step [T][B][H]

__device__ unsigned g_bar_cnt = 0;
__device__ volatile unsigned g_bar_gen = 0;

// ---------------- helpers ----------------
__device__ __forceinline__ float sigm(float x) {
    return 1.0f / (1.0f + __expf(-x));
}
__device__ __forceinline__ float tanh_f(float x) {
    float xx = fminf(15.0f, fmaxf(-15.0f, x));
    float t = __expf(-2.0f * xx);
    return (1.0f - t) / (1.0f + t);
}

__device__ __forceinline__ void grid_barrier() {
    __syncthreads();
    if (threadIdx.x == 0) {
        __threadfence();
        unsigned gen = g_bar_gen;
        if (atomicAdd(&g_bar_cnt, 1u) == NBLK - 1u) {
            atomicSub(&g_bar_cnt, (unsigned)NBLK);
            __threadfence();
            g_bar_gen = gen + 1u;
        } else {
            while (g_bar_gen == gen) { __nanosleep(20); }
            __threadfence();
        }
    }
    __syncthreads();
}

// copy one 64-col x 64-k weight chunk (16KB) global->smem, transposed layout.
// src: Wt[col][k] col-major rows; dst smem rows [col][68 words]
__device__ __forceinline__ void cp_chunk(unsigned dst_u32, const float* __restrict__ Wt,
                                         int kprow, int colp0, int k0) {
    const int tid = threadIdx.x;
#pragma unroll
    for (int i = 0; i < 4; i++) {
        int idx = tid + i * NTH;             // 0..1023
        int col = idx >> 4;
        int q4 = (idx & 15) << 2;
        const float* src = Wt + (colp0 + col) * kprow + k0 + q4;
        unsigned d = dst_u32 + (unsigned)((col * 68 + q4) * 4);
        asm volatile("cp.async.cg.shared.global [%0], [%1], 16;" :: "r"(d), "l"(src));
    }
    asm volatile("cp.async.commit_group;" ::: "memory");
}

// ---------------- LSTM tile: [16 batches x 64 gate-cols], all 128 CTAs ----------------
template <int KT, int NCH>
__device__ void lstm_tile(float* sm, unsigned sm_u32, int cta,
                          const float* __restrict__ x, int t,
                          const float* __restrict__ wv,
                          const float* __restrict__ hA,
                          const float* __restrict__ hB,
                          const float* __restrict__ Wt, int kprow,
                          const float* __restrict__ bsum,
                          float* __restrict__ cst,
                          float* __restrict__ hout) {
    const int tid = threadIdx.x;
    const int btile = cta >> 4;
    const int ctile = cta & 15;
    const int b_base = btile * 16;
    const int colp0 = ctile * 64;

    float* sact = sm + ACT_OFF;
    float* szs  = sm + ZS_OFF;

    // kick off first 3 weight chunks
    cp_chunk(sm_u32 + WT_OFF * 4 + 0 * WBUF_FLOATS * 4, Wt, kprow, colp0, 0);
    cp_chunk(sm_u32 + WT_OFF * 4 + 1 * WBUF_FLOATS * 4, Wt, kprow, colp0, 64);
    cp_chunk(sm_u32 + WT_OFF * 4 + 2 * WBUF_FLOATS * 4, Wt, kprow, colp0, 128);

    // ---- stage activations [bb][feat], all float4 coalesced ----
    // hA region: feat 68..323  (16 bb x 64 float4)
#pragma unroll
    for (int base = 0; base < 1024; base += NTH) {
        int id = base + tid;
        int bb = id >> 6, kq = id & 63;
        float4 v = *reinterpret_cast<const float4*>(hA + ((b_base + bb) << 8) + (kq << 2));
        *reinterpret_cast<float4*>(sact + bb * ACT_STRIDE + 68 + (kq << 2)) = v;
    }
    if (KT > 323) {
        // hB region: feat 324..579
#pragma unroll
        for (int base = 0; base < 1024; base += NTH) {
            int id = base + tid;
            int bb = id >> 6, kq = id & 63;
            float4 v = *reinterpret_cast<const float4*>(hB + ((b_base + bb) << 8) + (kq << 2));
            *reinterpret_cast<float4*>(sact + bb * ACT_STRIDE + 324 + (kq << 2)) = v;
        }
    }
    // w region: feat 4..67 (16 bb x 16 float4)
    {
        int bb = tid >> 4, kq = tid & 15;
        float4 v = *reinterpret_cast<const float4*>(wv + (b_base + bb) * 64 + (kq << 2));
        *reinterpret_cast<float4*>(sact + bb * ACT_STRIDE + 4 + (kq << 2)) = v;
    }
    // x region: feat 0..2 (48 scalars)
    if (tid < 48) {
        int bb = tid / 3, k = tid - bb * 3;
        sact[bb * ACT_STRIDE + k] = x[((b_base + bb) * Tn + t) * 3 + k];
    }

    const int cg = tid & 63;
    const int bg = tid >> 6;
    unsigned long long acc0 = 0ull, acc1 = 0ull, acc2 = 0ull, acc3 = 0ull;

    const float* ar0 = sact + (bg * 4 + 0) * ACT_STRIDE;
    const float* ar1 = sact + (bg * 4 + 1) * ACT_STRIDE;
    const float* ar2 = sact + (bg * 4 + 2) * ACT_STRIDE;
    const float* ar3 = sact + (bg * 4 + 3) * ACT_STRIDE;

    for (int c = 0; c < NCH; c++) {
        asm volatile("cp.async.wait_group 2;" ::: "memory");
        __syncthreads();
        const float* wb = sm + WT_OFF + (c % 3) * WBUF_FLOATS + cg * 68;
        const int kb = c * 64;
#pragma unroll 8
        for (int k2 = 0; k2 < 64; k2 += 4) {
            ulonglong2 wvv = *reinterpret_cast<const ulonglong2*>(wb + k2);
            ulonglong2 a0 = *reinterpret_cast<const ulonglong2*>(ar0 + kb + k2);
            ulonglong2 a1 = *reinterpret_cast<const ulonglong2*>(ar1 + kb + k2);
            ulonglong2 a2 = *reinterpret_cast<const ulonglong2*>(ar2 + kb + k2);
            ulonglong2 a3 = *reinterpret_cast<const ulonglong2*>(ar3 + kb + k2);
            asm("fma.rn.f32x2 %0, %1, %2, %0;" : "+l"(acc0) : "l"(a0.x), "l"(wvv.x));
            asm("fma.rn.f32x2 %0, %1, %2, %0;" : "+l"(acc1) : "l"(a1.x), "l"(wvv.x));
            asm("fma.rn.f32x2 %0, %1, %2, %0;" : "+l"(acc2) : "l"(a2.x), "l"(wvv.x));
            asm("fma.rn.f32x2 %0, %1, %2, %0;" : "+l"(acc3) : "l"(a3.x), "l"(wvv.x));
            asm("fma.rn.f32x2 %0, %1, %2, %0;" : "+l"(acc0) : "l"(a0.y), "l"(wvv.y));
            asm("fma.rn.f32x2 %0, %1, %2, %0;" : "+l"(acc1) : "l"(a1.y), "l"(wvv.y));
            asm("fma.rn.f32x2 %0, %1, %2, %0;" : "+l"(acc2) : "l"(a2.y), "l"(wvv.y));
            asm("fma.rn.f32x2 %0, %1, %2, %0;" : "+l"(acc3) : "l"(a3.y), "l"(wvv.y));
        }
        __syncthreads();
        if (c + 3 < NCH)
            cp_chunk(sm_u32 + WT_OFF * 4 + ((c + 3) % 3) * WBUF_FLOATS * 4,
                     Wt, kprow, colp0, (c + 3) * 64);
        else
            asm volatile("cp.async.commit_group;" ::: "memory");
    }

    float bias = __ldg(&bsum[colp0 + cg]);
    {
        float lo, hi;
        asm("mov.b64 {%0, %1}, %2;" : "=f"(lo), "=f"(hi) : "l"(acc0));
        szs[(bg * 4 + 0) * 64 + cg] = lo + hi + bias;
        asm("mov.b64 {%0, %1}, %2;" : "=f"(lo), "=f"(hi) : "l"(acc1));
        szs[(bg * 4 + 1) * 64 + cg] = lo + hi + bias;
        asm("mov.b64 {%0, %1}, %2;" : "=f"(lo), "=f"(hi) : "l"(acc2));
        szs[(bg * 4 + 2) * 64 + cg] = lo + hi + bias;
        asm("mov.b64 {%0, %1}, %2;" : "=f"(lo), "=f"(hi) : "l"(acc3));
        szs[(bg * 4 + 3) * 64 + cg] = lo + hi + bias;
    }
    __syncthreads();

    // cell update: 256 (b,hu) pairs
    {
        int b_loc = tid >> 4, hu_loc = tid & 15;
        int hu = ctile * 16 + hu_loc;
        int b = b_base + b_loc;
        float zi = szs[b_loc * 64 + hu_loc * 4 + 0];
        float zf = szs[b_loc * 64 + hu_loc * 4 + 1];
        float zg = szs[b_loc * 64 + hu_loc * 4 + 2];
        float zo = szs[b_loc * 64 + hu_loc * 4 + 3];
        int ix = (b << 8) + hu;
        float cp = cst[ix];
        float ig = sigm(zi), fg = sigm(zf), og = sigm(zo);
        float gg = tanh_f(zg);
        float cn = fmaf(fg, cp, ig * gg);
        cst[ix] = cn;
        hout[ix] = og * tanh_f(cn);
    }
    __syncthreads();
}

// ---------------- attention: 1 batch per CTA ----------------
__device__ void attn_tile(float* sm, int b, const float* __restrict__ h1,
                          float* __restrict__ wout,
                          const int* __restrict__ cidx,
                          const float* __restrict__ Ww,
                          const float* __restrict__ bw) {
    float* hrow = sm + ATTN_OFF;        // 256
    float* aw   = hrow + 256;           // 32
    float* kap  = aw + 32;              // 16
    float* phi  = kap + 16;             // 64
    int*   cs   = (int*)(phi + 64);     // 64
    float* part = (float*)(cs + 64);    // 240
    const int tt = threadIdx.x;

    hrow[tt] = __ldcv(&h1[(b << 8) + tt]);
    if (tt < 64) cs[tt] = __ldg(&cidx[b * 64 + tt]);
    __syncthreads();

    // projection: 30 outputs x 8 partials
    if (tt < 240) {
        int j = tt % 30, p = tt / 30;
        float z = 0.0f;
        const float* wp = Ww + p * 32 * 30 + j;
        const float* hp = hrow + p * 32;
#pragma unroll 8
        for (int i = 0; i < 32; i++)
            z = fmaf(hp[i], __ldg(&wp[i * 30]), z);
        part[p * 30 + j] = z;
    }
    __syncthreads();

    if (tt < 30) {
        float z = __ldg(&bw[tt]);
#pragma unroll
        for (int p = 0; p < 8; p++) z += part[p * 30 + tt];
        aw[tt] = __expf(z);
    }
    __syncthreads();

    if (tt < 10) {
        float kn = fmaf(0.1f, aw[20 + tt], g_kappa[b * 10 + tt]);
        g_kappa[b * 10 + tt] = kn;
        kap[tt] = kn;
    }
    __syncthreads();

    if (tt < 64) {
        float uu = (float)tt, ph = 0.0f;
#pragma unroll
        for (int k = 0; k < 10; k++) {
            float d = kap[k] - uu;
            ph = fmaf(aw[k], __expf(-aw[10 + k] * d * d), ph);
        }
        phi[tt] = ph;
    }
    __syncthreads();

    if (tt < 64) {
        float s = 0.0f;
        for (int u = 0; u < 64; u++)
            if (cs[u] == tt) s += phi[u];
        wout[b * 64 + tt] = s;
    }
    __syncthreads();
}

// ---------------- persistent RNN kernel ----------------
__global__ void __launch_bounds__(NTH)
rnn_kernel(const float* __restrict__ x, const int* __restrict__ cidx,
           const float* __restrict__ Ww, const float* __restrict__ bw) {
    extern __shared__ float sm[];
    unsigned sm_u32 = (unsigned)__cvta_generic_to_shared(sm);
    const int cta = blockIdx.x;
    const int tid = threadIdx.x;

    // zero act buffer once (NaN-safety for padded rows)
    for (int i = tid; i < 16 * ACT_STRIDE; i += NTH) sm[ACT_OFF + i] = 0.0f;

    // re-init recurrent state every launch (graph replays!)
    {
        int g0 = cta * NTH + tid;
        int gsz = NBLK * NTH;
        for (int p = g0; p < BH; p += gsz) {
            g_h1[0][p] = 0.f; g_h1[1][p] = 0.f;
            g_h2[0][p] = 0.f; g_h2[1][p] = 0.f;
            g_c1[p] = 0.f; g_c2[p] = 0.f; g_c3[p] = 0.f;
            g_zero[p] = 0.f;
        }
        for (int p = g0; p < Bn * An; p += gsz) { g_w[0][p] = 0.f; g_w[1][p] = 1.0f; }
        for (int p = g0; p < Bn * Kw; p += gsz) g_kappa[p] = 0.f;
    }
    grid_barrier();

    // prologue: LSTM1(0): w(-1)=ones (g_w[1]), h1(-1)=0 -> h1(0)=g_h1[0]
    lstm_tile<323, 6>(sm, sm_u32, cta, x, 0, g_w[1], g_h1[1], g_zero,
                      g_W1t, 384, g_b1, g_c1, g_h1[0]);
    grid_barrier();
    attn_tile(sm, cta, g_h1[0], g_w[0], cidx, Ww, bw);
    grid_barrier();

    for (int t = 0; t < Tn; t++) {
        const int p = t & 1, pn = (t + 1) & 1;

        // slot A: LSTM2(t) then LSTM1(t+1)
        lstm_tile<579, 10>(sm, sm_u32, cta, x, t, g_w[p], g_h1[p], g_h2[pn],
                           g_W2t, 640, g_b2, g_c2, g_h2[p]);
        if (t + 1 < Tn)
            lstm_tile<323, 6>(sm, sm_u32, cta, x, t + 1, g_w[p], g_h1[p], g_zero,
                              g_W1t, 384, g_b1, g_c1, g_h1[pn]);
        grid_barrier();

        // slot B: LSTM3(t) then Attn(t+1)
        {
            const float* h3prev = (t > 0) ? (g_out + (t - 1) * BH) : g_zero;
            lstm_tile<579, 10>(sm, sm_u32, cta, x, t, g_w[p], g_h2[p], h3prev,
                               g_W3t, 640, g_b3, g_c3, g_out + t * BH);
        }
        if (t + 1 < Tn)
            attn_tile(sm, cta, g_h1[pn], g_w[pn], cidx, Ww, bw);
        grid_barrier();
    }
}

// ---------------- weight pre-pack kernel (transposed col-major, padded features) ----
__global__ void prep_kernel(
    const float* Wih1, const float* Whh1, const float* bih1, const float* bhh1,
    const float* Wih2, const float* Whh2, const float* bih2, const float* bhh2,
    const float* Wih3, const float* Whh3, const float* bih3, const float* bhh3,
    const float* We, const float* be, const float* Wpi, const float* bpi,
    const float* Wmu1, const float* bmu1, const float* Wmu2, const float* bmu2,
    const float* Ws1, const float* bs1, const float* Ws2, const float* bs2,
    const float* Wrho, const float* brho) {
    int g0 = blockIdx.x * blockDim.x + threadIdx.x;
    int gsz = gridDim.x * blockDim.x;

    // W1: kprow=384. feat: 0-2 x->Wih1[feat], 3 pad, 4-67 -> Wih1[feat-1], 68-323 -> Whh1[feat-68]
    for (int pidx = g0; pidx < 1024 * 384; pidx += gsz) {
        int colp = pidx / 384, feat = pidx - colp * 384;
        int hu = colp >> 2, g = colp & 3;
        int j = g * 256 + hu;
        float v = 0.f;
        if (feat < 3)        v = Wih1[feat * 1024 + j];
        else if (feat == 3)  v = 0.f;
        else if (feat < 68)  v = Wih1[(feat - 1) * 1024 + j];
        else if (feat < 324) v = Whh1[(feat - 68) * 1024 + j];
        g_W1t[pidx] = v;
    }
    // W2/W3: kprow=640. feat: 0-2 Wih[feat], 3 pad, 4-323 Wih[feat-1], 324-579 Whh[feat-324]
    for (int pidx = g0; pidx < 1024 * 640; pidx += gsz) {
        int colp = pidx / 640, feat = pidx - colp * 640;
        int hu = colp >> 2, g = colp & 3;
        int j = g * 256 + hu;
        float v2 = 0.f, v3 = 0.f;
        if (feat < 3) {
            v2 = Wih2[feat * 1024 + j]; v3 = Wih3[feat * 1024 + j];
        } else if (feat >= 4 && feat < 324) {
            v2 = Wih2[(feat - 1) * 1024 + j]; v3 = Wih3[(feat - 1) * 1024 + j];
        } else if (feat >= 324 && feat < 580) {
            v2 = Whh2[(feat - 324) * 1024 + j]; v3 = Whh3[(feat - 324) * 1024 + j];
        }
        g_W2t[pidx] = v2;
        g_W3t[pidx] = v3;
    }
    for (int colp = g0; colp < 1024; colp += gsz) {
        int hu = colp >> 2, g = colp & 3;
        int j = g * 256 + hu;
        g_b1[colp] = bih1[j] + bhh1[j];
        g_b2[colp] = bih2[j] + bhh2[j];
        g_b3[colp] = bih3[j] + bhh3[j];
    }
    for (int pidx = g0; pidx < 256 * 121; pidx += gsz) {
        int i = pidx / 121, col = pidx - i * 121;
        float v;
        if (col == 0)       v = We[i];
        else if (col < 21)  v = Wpi[i * 20 + (col - 1)];
        else if (col < 41)  v = Wmu1[i * 20 + (col - 21)];
        else if (col < 61)  v = Wmu2[i * 20 + (col - 41)];
        else if (col < 81)  v = Ws1[i * 20 + (col - 61)];
        else if (col < 101) v = Ws2[i * 20 + (col - 81)];
        else                v = Wrho[i * 20 + (col - 101)];
        g_Wh[pidx] = v;
    }
    for (int col = g0; col < 121; col += gsz) {
        float v;
        if (col == 0)       v = be[0];
        else if (col < 21)  v = bpi[col - 1];
        else if (col < 41)  v = bmu1[col - 21];
        else if (col < 61)  v = bmu2[col - 41];
        else if (col < 81)  v = bs1[col - 61];
        else if (col < 101) v = bs2[col - 81];
        else                v = brho[col - 101];
        g_bh[col] = v;
    }
}

// ---------------- MDN heads kernel ----------------
__global__ void __launch_bounds__(128)
heads_kernel(float* __restrict__ out) {
    __shared__ __align__(16) float hs[32 * 256];
    __shared__ float pz[32][20];
    const int r0 = blockIdx.x * 32;
    const int tid = threadIdx.x;

    {
        const float4* src = reinterpret_cast<const float4*>(g_out + r0 * 256);
        float4* dst = reinterpret_cast<float4*>(hs);
        for (int pidx = tid; pidx < 32 * 64; pidx += 128) dst[pidx] = src[pidx];
    }
    __syncthreads();

    const int j = tid;
    float acc[32];
    if (j < 121) {
#pragma unroll
        for (int r = 0; r < 32; r++) acc[r] = 0.0f;
#pragma unroll 2
        for (int i4 = 0; i4 < 64; i4++) {
            float w0 = g_Wh[(i4 * 4 + 0) * 121 + j];
            float w1 = g_Wh[(i4 * 4 + 1) * 121 + j];
            float w2 = g_Wh[(i4 * 4 + 2) * 121 + j];
            float w3 = g_Wh[(i4 * 4 + 3) * 121 + j];
#pragma unroll
            for (int r = 0; r < 32; r++) {
                float4 hv = reinterpret_cast<const float4*>(hs + r * 256)[i4];
                acc[r] = fmaf(hv.x, w0, fmaf(hv.y, w1, fmaf(hv.z, w2, fmaf(hv.w, w3, acc[r]))));
            }
        }
        float bias = g_bh[j];
#pragma unroll
        for (int r = 0; r < 32; r++) acc[r] += bias;
        if (j >= 1 && j < 21)
            for (int r = 0; r < 32; r++) pz[r][j - 1] = acc[r];
    }
    __syncthreads();

    if (j < 121) {
        const int TB = Tn * Bn;
        float* es  = out;
        float* pi  = out + TB;
        float* mu1 = out + TB + TB * 20;
        float* mu2 = mu1 + TB * 20;
        float* s1  = mu2 + TB * 20;
        float* s2  = s1 + TB * 20;
        float* rh  = s2 + TB * 20;
        for (int r = 0; r < 32; r++) {
            int gr = r0 + r;
            float z = acc[r];
            if (j == 0) {
                es[gr] = 1.0f / (1.0f + __expf(z));
            } else if (j < 21) {
                float m = -1e30f;
                for (int k = 0; k < 20; k++) m = fmaxf(m, pz[r][k]);
                float s = 0.f;
                for (int k = 0; k < 20; k++) s += __expf(pz[r][k] - m);
                pi[gr * 20 + (j - 1)] = __expf(z - m) / s;
            } else if (j < 41) {
                mu1[gr * 20 + (j - 21)] = z;
            } else if (j < 61) {
                mu2[gr * 20 + (j - 41)] = z;
            } else if (j < 81) {
                s1[gr * 20 + (j - 61)] = __expf(z);
            } else if (j < 101) {
                s2[gr * 20 + (j - 81)] = __expf(z);
            } else {
                rh[gr * 20 + (j - 101)] = tanh_f(z);
            }
        }
    }
}

// ---------------- launch ----------------
extern "C" void kernel_launch(void* const* d_in, const int* in_sizes, int n_in,
                              void* d_out, int out_size) {
    const float* x    = (const float*)d_in[0];
    const int*   c    = (const int*)d_in[1];
    const float* Wih1 = (const float*)d_in[2];
    const float* Whh1 = (const float*)d_in[3];
    const float* bih1 = (const float*)d_in[4];
    const float* bhh1 = (const float*)d_in[5];
    const float* Wih2 = (const float*)d_in[6];
    const float* Whh2 = (const float*)d_in[7];
    const float* bih2 = (const float*)d_in[8];
    const float* bhh2 = (const float*)d_in[9];
    const float* Wih3 = (const float*)d_in[10];
    const float* Whh3 = (const float*)d_in[11];
    const float* bih3 = (const float*)d_in[12];
    const float* bhh3 = (const float*)d_in[13];
    const float* Ww   = (const float*)d_in[14];
    const float* bw   = (const float*)d_in[15];
    const float* We   = (const float*)d_in[16];
    const float* be   = (const float*)d_in[17];
    const float* Wpi  = (const float*)d_in[18];
    const float* bpi  = (const float*)d_in[19];
    const float* Wmu1 = (const float*)d_in[20];
    const float* bmu1 = (const float*)d_in[21];
    const float* Wmu2 = (const float*)d_in[22];
    const float* bmu2 = (const float*)d_in[23];
    const float* Ws1  = (const float*)d_in[24];
    const float* bs1  = (const float*)d_in[25];
    const float* Ws2  = (const float*)d_in[26];
    const float* bs2  = (const float*)d_in[27];
    const float* Wrho = (const float*)d_in[28];
    const float* brho = (const float*)d_in[29];

    cudaFuncSetAttribute(rnn_kernel, cudaFuncAttributeMaxDynamicSharedMemorySize,
                         SMEM_BYTES);

    prep_kernel<<<512, 256>>>(Wih1, Whh1, bih1, bhh1,
                              Wih2, Whh2, bih2, bhh2,
                              Wih3, Whh3, bih3, bhh3,
                              We, be, Wpi, bpi, Wmu1, bmu1, Wmu2, bmu2,
                              Ws1, bs1, Ws2, bs2, Wrho, brho);
    rnn_kernel<<<NBLK, NTH, SMEM_BYTES>>>(x, c, Ww, bw);
    heads_kernel<<<(Tn * Bn) / 32, 128>>>((float*)d_out);
}